// round 15
// baseline (speedup 1.0000x reference)
#include <cuda_runtime.h>
#include <cuda_bf16.h>

// Problem constants (shapes fixed by the dataset)
#define NNODES 100000
#define FDIM   128
#define NFK    (NNODES * FDIM)   // 12,800,000 floats per feature matrix

// Scratch: Chebyshev feature matrices T1, T2, T3 and transposed weights.
// (__device__ globals are the sanctioned scratch mechanism — no allocs.)
__device__ float g_T1[NFK];
__device__ float g_T2[NFK];
__device__ float g_T3[NFK];
__device__ float g_Wt[512 * 128];   // Wt[c][o] = W[o][c]

// ---------------------------------------------------------------------------
// init: T1 = 0, T2 = -x   (T2 pre-initialized so spmm with scale=2 yields
//                          T2 = 2*L*T1 - x directly)
// ---------------------------------------------------------------------------
__global__ void __launch_bounds__(256) init_kernel(const float4* __restrict__ x,
                                                   int n4) {
    int i = blockIdx.x * 256 + threadIdx.x;
    if (i < n4) {
        ((float4*)g_T1)[i] = make_float4(0.f, 0.f, 0.f, 0.f);
        float4 v = x[i];
        ((float4*)g_T2)[i] = make_float4(-v.x, -v.y, -v.z, -v.w);
    }
}

// T3 = -T1 (must run after spmm1 finalized T1)
__global__ void __launch_bounds__(256) neg_kernel(int n4) {
    int i = blockIdx.x * 256 + threadIdx.x;
    if (i < n4) {
        float4 v = ((const float4*)g_T1)[i];
        ((float4*)g_T3)[i] = make_float4(-v.x, -v.y, -v.z, -v.w);
    }
}

// W transpose: Wt[c][o] = W[o][c].  W is [128][512].
__global__ void __launch_bounds__(256) wt_kernel(const float* __restrict__ W) {
    int i = blockIdx.x * 256 + threadIdx.x;   // 0..65535
    int o = i >> 9;        // 0..127
    int c = i & 511;       // 0..511
    g_Wt[c * 128 + o] = W[i];
}

// ---------------------------------------------------------------------------
// SpMM:  Y[rows[e], :] += scale * vals[e] * X[cols[e], :]
// One warp per edge (32 lanes x float4 = 128 floats). Indices staged through
// smem for coalesced loads; scatter via no-return vector RED.
// ---------------------------------------------------------------------------
__global__ void __launch_bounds__(256) spmm_kernel(
    const int*   __restrict__ rows,
    const int*   __restrict__ cols,
    const float* __restrict__ vals,
    const float4* __restrict__ X,
    float4*       __restrict__ Y,
    float scale, int nE)
{
    __shared__ int   s_r[256];
    __shared__ int   s_c[256];
    __shared__ float s_v[256];

    int base = blockIdx.x * 256;
    int tid  = threadIdx.x;
    int rem  = nE - base;
    if (rem > 256) rem = 256;
    if (tid < rem) {
        s_r[tid] = rows[base + tid];
        s_c[tid] = cols[base + tid];
        s_v[tid] = vals[base + tid] * scale;
    }
    __syncthreads();

    int lane = tid & 31;
    int warp = tid >> 5;
    int e0   = warp * 32;
    int cnt  = rem - e0;
    if (cnt > 32) cnt = 32;

    for (int j = 0; j < cnt; ++j) {
        int e = e0 + j;
        float v = s_v[e];
        int   c = s_c[e];
        int   r = s_r[e];
        float4 xv = __ldg(&X[c * 32 + lane]);
        float4 p  = make_float4(xv.x * v, xv.y * v, xv.z * v, xv.w * v);
        float4* dst = &Y[r * 32 + lane];
        asm volatile("red.global.add.v4.f32 [%0], {%1,%2,%3,%4};"
                     :: "l"(dst), "f"(p.x), "f"(p.y), "f"(p.z), "f"(p.w)
                     : "memory");
    }
}

// ---------------------------------------------------------------------------
// GEMM: out[n][o] = b[o] + sum_f sum_ord T_ord[n][f] * W[o][f*4+ord]
// Block tile 128(M) x 128(N full), K=512 in 4 stages of 128 (32 feats x 4 ord).
// 256 threads, 8x8 register tile each. Conflict-free smem patterns:
//   sA[ord][128 rows][32 feats]  (natural layout; a-loads broadcast over tx)
//   sW[128 kk][128 o]            (from pre-transposed Wt; w-loads stride-1)
// ---------------------------------------------------------------------------
__global__ void __launch_bounds__(256, 1) gemm_kernel(
    const float* __restrict__ A0,
    const float* __restrict__ bias,
    float* __restrict__ out, int nNodes)
{
    extern __shared__ float sm[];
    float* sA = sm;                  // 4*128*32 = 16384 floats
    float* sW = sm + 4 * 128 * 32;   // 128*128  = 16384 floats

    int tid = threadIdx.x;
    int tx  = tid & 15;    // column group: cols tx + 16*j
    int ty  = tid >> 4;    // row group:    rows ty*8 + i
    int m0  = blockIdx.x * 128;

    float acc[8][8];
#pragma unroll
    for (int j = 0; j < 8; ++j) {
        float bj = __ldg(&bias[tx + 16 * j]);
#pragma unroll
        for (int i = 0; i < 8; ++i) acc[i][j] = bj;
    }

    const float* Abuf0 = A0;
    const float* Abuf1 = g_T1;
    const float* Abuf2 = g_T2;
    const float* Abuf3 = g_T3;

    for (int fc = 0; fc < 4; ++fc) {
        __syncthreads();
        // ---- load A tiles: for each ord, 128 rows x 32 feats (8 float4/row)
#pragma unroll
        for (int ord = 0; ord < 4; ++ord) {
            const float* Ab = (ord == 0) ? Abuf0 : (ord == 1) ? Abuf1
                             : (ord == 2) ? Abuf2 : Abuf3;
            const float4* src = (const float4*)Ab;
#pragma unroll
            for (int t = 0; t < 4; ++t) {
                int i   = tid + t * 256;         // 0..1023
                int row = i >> 3;
                int fq  = i & 7;
                int gr  = m0 + row;
                if (gr >= nNodes) gr = nNodes - 1;   // clamp; store is guarded
                float4 v = __ldg(&src[gr * 32 + fc * 8 + fq]);
                *(float4*)&sA[(ord * 128 + row) * 32 + fq * 4] = v;
            }
        }
        // ---- load W tile: 128 kk x 128 o (already transposed in g_Wt)
        {
            const float4* src = (const float4*)g_Wt;
#pragma unroll
            for (int t = 0; t < 16; ++t) {
                int i  = tid + t * 256;          // 0..4095
                int kk = i >> 5;
                int o4 = i & 31;
                float4 v = src[(fc * 128 + kk) * 32 + o4];
                *(float4*)&sW[kk * 128 + o4 * 4] = v;
            }
        }
        __syncthreads();

        // ---- compute: 128 local k-values
        for (int f = 0; f < 32; ++f) {
#pragma unroll
            for (int ord = 0; ord < 4; ++ord) {
                int kk = f * 4 + ord;
                float a[8], w[8];
#pragma unroll
                for (int i = 0; i < 8; ++i)
                    a[i] = sA[(ord * 128 + ty * 8 + i) * 32 + f];
#pragma unroll
                for (int j = 0; j < 8; ++j)
                    w[j] = sW[kk * 128 + tx + 16 * j];
#pragma unroll
                for (int i = 0; i < 8; ++i)
#pragma unroll
                    for (int j = 0; j < 8; ++j)
                        acc[i][j] = fmaf(a[i], w[j], acc[i][j]);
            }
        }
    }

    // ---- store
#pragma unroll
    for (int i = 0; i < 8; ++i) {
        int gr = m0 + ty * 8 + i;
        if (gr < nNodes) {
#pragma unroll
            for (int j = 0; j < 8; ++j)
                out[gr * 128 + tx + 16 * j] = acc[i][j];
        }
    }
}

// ---------------------------------------------------------------------------
// Launch. Inputs (metadata order): x, lap_rows, lap_cols, lap_vals, W, b, k
// ---------------------------------------------------------------------------
extern "C" void kernel_launch(void* const* d_in, const int* in_sizes, int n_in,
                              void* d_out, int out_size) {
    const float* x    = (const float*)d_in[0];
    const int*   rows = (const int*)  d_in[1];
    const int*   cols = (const int*)  d_in[2];
    const float* vals = (const float*)d_in[3];
    const float* W    = (const float*)d_in[4];
    const float* b    = (const float*)d_in[5];
    float* out = (float*)d_out;

    int nNodes = in_sizes[0] / FDIM;     // 100000
    int E      = in_sizes[1];            // 3,200,000
    int n4     = nNodes * (FDIM / 4);    // float4 count

    float *T1, *T2, *T3;
    cudaGetSymbolAddress((void**)&T1, g_T1);
    cudaGetSymbolAddress((void**)&T2, g_T2);
    cudaGetSymbolAddress((void**)&T3, g_T3);

    cudaFuncSetAttribute(gemm_kernel,
                         cudaFuncAttributeMaxDynamicSharedMemorySize, 131072);

    int nb4 = (n4 + 255) / 256;
    int eb  = (E + 255) / 256;

    // T1 = 0, T2 = -x ; Wt = W^T
    init_kernel<<<nb4, 256>>>((const float4*)x, n4);
    wt_kernel<<<256, 256>>>(W);

    // T1 = L x
    spmm_kernel<<<eb, 256>>>(rows, cols, vals, (const float4*)x,
                             (float4*)T1, 1.0f, E);
    // T3 = -T1
    neg_kernel<<<nb4, 256>>>(n4);
    // T2 = 2 L T1 - x   (T2 was -x)
    spmm_kernel<<<eb, 256>>>(rows, cols, vals, (const float4*)T1,
                             (float4*)T2, 2.0f, E);
    // T3 = 2 L T2 - T1  (T3 was -T1)
    spmm_kernel<<<eb, 256>>>(rows, cols, vals, (const float4*)T2,
                             (float4*)T3, 2.0f, E);

    // out = [x|T1|T2|T3]_(f*4+ord) @ W^T + b
    gemm_kernel<<<(nNodes + 127) / 128, 256, 131072>>>(x, b, out, nNodes);
}

// round 16
// speedup vs baseline: 1.2549x; 1.2549x over previous
#include <cuda_runtime.h>
#include <cuda_bf16.h>
#include <cstdint>

// Problem constants (shapes fixed by the dataset)
#define NNODES 100000
#define FDIM   128
#define NFK    (NNODES * FDIM)   // 12,800,000 floats per feature matrix

// Scratch (device globals = sanctioned scratch; no allocs allowed)
__device__ float g_T1[NFK];
__device__ float g_T2[NFK];
__device__ float g_T3[NFK];
// Wt2[k'][o] = tf32(W[o][ (k'%128)*4 + k'/128 ]),  k' = ord*128 + f
__device__ float g_Wt[512 * 128];

__device__ __forceinline__ float to_tf32(float x) {
    float r;
    asm("cvt.rna.tf32.f32 %0, %1;" : "=f"(r) : "f"(x));
    return r;
}

// ---------------------------------------------------------------------------
// init: T1 = 0, T2 = -x   (T2 pre-init so spmm(scale=2) yields 2*L*T1 - x)
// ---------------------------------------------------------------------------
__global__ void __launch_bounds__(256) init_kernel(const float4* __restrict__ x,
                                                   int n4) {
    int i = blockIdx.x * 256 + threadIdx.x;
    if (i < n4) {
        ((float4*)g_T1)[i] = make_float4(0.f, 0.f, 0.f, 0.f);
        float4 v = x[i];
        ((float4*)g_T2)[i] = make_float4(-v.x, -v.y, -v.z, -v.w);
    }
}

// T3 = -T1 (after spmm1 finalized T1)
__global__ void __launch_bounds__(256) neg_kernel(int n4) {
    int i = blockIdx.x * 256 + threadIdx.x;
    if (i < n4) {
        float4 v = ((const float4*)g_T1)[i];
        ((float4*)g_T3)[i] = make_float4(-v.x, -v.y, -v.z, -v.w);
    }
}

// W permute+transpose+tf32-round. W is [128][512], col index c = f*4+ord.
__global__ void __launch_bounds__(256) wt_kernel(const float* __restrict__ W) {
    int i = blockIdx.x * 256 + threadIdx.x;   // 0..65535
    int o   = i >> 9;        // 0..127
    int c   = i & 511;       // 0..511
    int f   = c >> 2;
    int ord = c & 3;
    g_Wt[(ord * 128 + f) * 128 + o] = to_tf32(W[i]);
}

// ---------------------------------------------------------------------------
// SpMM:  Y[rows[e], :] += scale * vals[e] * X[cols[e], :]
// One warp per edge (32 lanes x float4). Indices staged in smem; scatter via
// no-return vector RED (L2 atomic).
// ---------------------------------------------------------------------------
__global__ void __launch_bounds__(256) spmm_kernel(
    const int*   __restrict__ rows,
    const int*   __restrict__ cols,
    const float* __restrict__ vals,
    const float4* __restrict__ X,
    float4*       __restrict__ Y,
    float scale, int nE)
{
    __shared__ int   s_r[256];
    __shared__ int   s_c[256];
    __shared__ float s_v[256];

    int base = blockIdx.x * 256;
    int tid  = threadIdx.x;
    int rem  = nE - base;
    if (rem > 256) rem = 256;
    if (tid < rem) {
        s_r[tid] = rows[base + tid];
        s_c[tid] = cols[base + tid];
        s_v[tid] = vals[base + tid] * scale;
    }
    __syncthreads();

    int lane = tid & 31;
    int warp = tid >> 5;
    int e0   = warp * 32;
    int cnt  = rem - e0;
    if (cnt > 32) cnt = 32;

    for (int j = 0; j < cnt; ++j) {
        int e = e0 + j;
        float v = s_v[e];
        int   c = s_c[e];
        int   r = s_r[e];
        float4 xv = __ldg(&X[c * 32 + lane]);
        float4 p  = make_float4(xv.x * v, xv.y * v, xv.z * v, xv.w * v);
        float4* dst = &Y[r * 32 + lane];
        asm volatile("red.global.add.v4.f32 [%0], {%1,%2,%3,%4};"
                     :: "l"(dst), "f"(p.x), "f"(p.y), "f"(p.z), "f"(p.w)
                     : "memory");
    }
}

// ---------------------------------------------------------------------------
// tf32 tensor-core GEMM:
//   out[n][o] = b[o] + sum_{k'=0..511} A[n][k'] * Wt2[k'][o]
// where A = [x | T1 | T2 | T3] concatenated along K (k' = ord*128 + f).
//
// Block: 256 thr = 8 warps (4 M x 2 N), block tile 128(M) x 128(N),
// K chunks of 32. Warp tile 32x64 -> 2 m-tiles x 8 n-tiles of m16n8k8.
// smem strides: SA=36 -> a-frag bank (4r+k)%32 bijective over warp;
//               SW=136 -> b-frag bank (8k+o)%32 bijective. Conflict-free.
// ---------------------------------------------------------------------------
#define SA 36
#define SW 136

__global__ void __launch_bounds__(256, 2) gemm_kernel(
    const float* __restrict__ A0,
    const float* __restrict__ bias,
    float* __restrict__ out, int nNodes)
{
    __shared__ float sA[128 * SA];  // 18432 B
    __shared__ float sW[32  * SW];  // 17408 B

    const uint32_t* sAu = (const uint32_t*)sA;
    const uint32_t* sWu = (const uint32_t*)sW;

    int tid  = threadIdx.x;
    int lane = tid & 31;
    int warp = tid >> 5;
    int wm   = warp >> 1;          // 0..3
    int wn   = warp & 1;           // 0..1
    int m0   = blockIdx.x * 128;

    int g  = lane >> 2;            // groupID 0..7
    int tg = lane & 3;             // threadID in group 0..3

    float acc[2][8][4];
#pragma unroll
    for (int mt = 0; mt < 2; ++mt)
#pragma unroll
        for (int nt = 0; nt < 8; ++nt)
#pragma unroll
            for (int r = 0; r < 4; ++r) acc[mt][nt][r] = 0.f;

    const float* Abufs[4] = { A0, g_T1, g_T2, g_T3 };

#pragma unroll 1
    for (int ord = 0; ord < 4; ++ord) {
        const float4* Ab = (const float4*)Abufs[ord];
#pragma unroll 1
        for (int cc = 0; cc < 4; ++cc) {
            int kc = cc * 32;               // k offset within this ord buffer
            int kb = ord * 128 + kc;        // global k' base for W
            __syncthreads();
            // ---- fill sA: 128 rows x 32 k (tf32-rounded)
#pragma unroll
            for (int t = 0; t < 4; ++t) {
                int i   = tid + t * 256;    // 0..1023
                int row = i >> 3;
                int fq  = i & 7;
                int gr  = m0 + row;
                if (gr >= nNodes) gr = nNodes - 1;   // clamp; stores guarded
                float4 v = __ldg(&Ab[gr * 32 + (kc >> 2) + fq]);
                float* d = &sA[row * SA + fq * 4];
                d[0] = to_tf32(v.x); d[1] = to_tf32(v.y);
                d[2] = to_tf32(v.z); d[3] = to_tf32(v.w);
            }
            // ---- fill sW: 32 k x 128 o (already tf32 in g_Wt)
            {
                const float4* src = (const float4*)g_Wt;
#pragma unroll
                for (int t = 0; t < 4; ++t) {
                    int i  = tid + t * 256;  // 0..1023
                    int k  = i >> 5;
                    int o4 = i & 31;
                    float4 v = src[(kb + k) * 32 + o4];
                    *(float4*)&sW[k * SW + o4 * 4] = v;
                }
            }
            __syncthreads();

            // ---- compute: 4 k8 steps
#pragma unroll
            for (int ks = 0; ks < 4; ++ks) {
                int k0 = ks * 8;
                uint32_t a[2][4];
#pragma unroll
                for (int mt = 0; mt < 2; ++mt) {
                    int r = wm * 32 + mt * 16 + g;
                    a[mt][0] = sAu[ r      * SA + k0 + tg    ];
                    a[mt][1] = sAu[(r + 8) * SA + k0 + tg    ];
                    a[mt][2] = sAu[ r      * SA + k0 + tg + 4];
                    a[mt][3] = sAu[(r + 8) * SA + k0 + tg + 4];
                }
#pragma unroll
                for (int nt = 0; nt < 8; ++nt) {
                    int col = wn * 64 + nt * 8 + g;
                    uint32_t b0 = sWu[(k0 + tg    ) * SW + col];
                    uint32_t b1 = sWu[(k0 + tg + 4) * SW + col];
#pragma unroll
                    for (int mt = 0; mt < 2; ++mt) {
                        asm volatile(
                            "mma.sync.aligned.m16n8k8.row.col.f32.tf32.tf32.f32 "
                            "{%0,%1,%2,%3}, {%4,%5,%6,%7}, {%8,%9}, {%0,%1,%2,%3};"
                            : "+f"(acc[mt][nt][0]), "+f"(acc[mt][nt][1]),
                              "+f"(acc[mt][nt][2]), "+f"(acc[mt][nt][3])
                            : "r"(a[mt][0]), "r"(a[mt][1]),
                              "r"(a[mt][2]), "r"(a[mt][3]),
                              "r"(b0), "r"(b1));
                    }
                }
            }
        }
    }

    // ---- epilogue: add bias, store (c0,c1) and (c2,c3) as float2
#pragma unroll
    for (int nt = 0; nt < 8; ++nt) {
        int col = wn * 64 + nt * 8 + tg * 2;
        float b0 = __ldg(&bias[col]);
        float b1 = __ldg(&bias[col + 1]);
#pragma unroll
        for (int mt = 0; mt < 2; ++mt) {
            int row = m0 + wm * 32 + mt * 16 + g;
            if (row < nNodes) {
                float2 v0 = make_float2(acc[mt][nt][0] + b0, acc[mt][nt][1] + b1);
                *(float2*)&out[row * 128 + col] = v0;
            }
            if (row + 8 < nNodes) {
                float2 v1 = make_float2(acc[mt][nt][2] + b0, acc[mt][nt][3] + b1);
                *(float2*)&out[(row + 8) * 128 + col] = v1;
            }
        }
    }
}

// ---------------------------------------------------------------------------
// Launch. Inputs (metadata order): x, lap_rows, lap_cols, lap_vals, W, b, k
// ---------------------------------------------------------------------------
extern "C" void kernel_launch(void* const* d_in, const int* in_sizes, int n_in,
                              void* d_out, int out_size) {
    const float* x    = (const float*)d_in[0];
    const int*   rows = (const int*)  d_in[1];
    const int*   cols = (const int*)  d_in[2];
    const float* vals = (const float*)d_in[3];
    const float* W    = (const float*)d_in[4];
    const float* b    = (const float*)d_in[5];
    float* out = (float*)d_out;

    int nNodes = in_sizes[0] / FDIM;     // 100000
    int E      = in_sizes[1];            // 3,200,000
    int n4     = nNodes * (FDIM / 4);

    float *T1, *T2, *T3;
    cudaGetSymbolAddress((void**)&T1, g_T1);
    cudaGetSymbolAddress((void**)&T2, g_T2);
    cudaGetSymbolAddress((void**)&T3, g_T3);

    int nb4 = (n4 + 255) / 256;
    int eb  = (E + 255) / 256;

    // T1 = 0, T2 = -x ; Wt2 = permuted tf32 W^T
    init_kernel<<<nb4, 256>>>((const float4*)x, n4);
    wt_kernel<<<256, 256>>>(W);

    // T1 = L x
    spmm_kernel<<<eb, 256>>>(rows, cols, vals, (const float4*)x,
                             (float4*)T1, 1.0f, E);
    // T3 = -T1
    neg_kernel<<<nb4, 256>>>(n4);
    // T2 = 2 L T1 - x
    spmm_kernel<<<eb, 256>>>(rows, cols, vals, (const float4*)T1,
                             (float4*)T2, 2.0f, E);
    // T3 = 2 L T2 - T1
    spmm_kernel<<<eb, 256>>>(rows, cols, vals, (const float4*)T2,
                             (float4*)T3, 2.0f, E);

    // out = [x|T1|T2|T3] @ Wt2 + b   (tf32 tensor cores)
    gemm_kernel<<<(nNodes + 127) / 128, 256>>>(x, b, out, nNodes);
}

// round 17
// speedup vs baseline: 2.0884x; 1.6643x over previous
#include <cuda_runtime.h>
#include <cuda_bf16.h>
#include <cstdint>

// Problem constants (shapes fixed by the dataset)
#define NNODES 100000
#define FDIM   128
#define NFK    (NNODES * FDIM)   // 12,800,000 floats per feature matrix
#define EMAX   3200000

// Scratch (device globals = sanctioned scratch; no allocs allowed)
__device__ float g_T1[NFK];
__device__ float g_T2[NFK];
__device__ float g_T3[NFK];
__device__ float g_Wt[512 * 128];     // permuted tf32 W^T
// Edge sort scratch (sorted-by-row copy of the COO structure)
__device__ int   g_srow[EMAX];
__device__ int   g_scol[EMAX];
__device__ float g_sval[EMAX];
__device__ int   g_cnt[NNODES];       // histogram
__device__ int   g_off[NNODES];       // running offsets (consumed by scatter)
__device__ int   g_bsum[128];         // scan block totals
__device__ int   g_bsumx[128];        // exclusive-scanned totals

#define SCAN_B 1024
#define NBLK   ((NNODES + SCAN_B - 1) / SCAN_B)   // 98

__device__ __forceinline__ float to_tf32(float x) {
    float r;
    asm("cvt.rna.tf32.f32 %0, %1;" : "=f"(r) : "f"(x));
    return r;
}

// ---------------------------------------------------------------------------
// init: T1 = 0, T2 = -x, zero histogram
// ---------------------------------------------------------------------------
__global__ void __launch_bounds__(256) init_kernel(const float4* __restrict__ x,
                                                   int n4) {
    int i = blockIdx.x * 256 + threadIdx.x;
    if (i < n4) {
        ((float4*)g_T1)[i] = make_float4(0.f, 0.f, 0.f, 0.f);
        float4 v = x[i];
        ((float4*)g_T2)[i] = make_float4(-v.x, -v.y, -v.z, -v.w);
    }
    if (i < NNODES) g_cnt[i] = 0;
}

// T3 = -T1 (after spmm1 finalized T1)
__global__ void __launch_bounds__(256) neg_kernel(int n4) {
    int i = blockIdx.x * 256 + threadIdx.x;
    if (i < n4) {
        float4 v = ((const float4*)g_T1)[i];
        ((float4*)g_T3)[i] = make_float4(-v.x, -v.y, -v.z, -v.w);
    }
}

// W permute+transpose+tf32-round. W is [128][512], col index c = f*4+ord.
__global__ void __launch_bounds__(256) wt_kernel(const float* __restrict__ W) {
    int i = blockIdx.x * 256 + threadIdx.x;   // 0..65535
    int o   = i >> 9;
    int c   = i & 511;
    int f   = c >> 2;
    int ord = c & 3;
    g_Wt[(ord * 128 + f) * 128 + o] = to_tf32(W[i]);
}

// ---------------------------------------------------------------------------
// Counting sort of edges by destination row
// ---------------------------------------------------------------------------
__global__ void __launch_bounds__(256) hist_kernel(const int* __restrict__ rows,
                                                   int nE) {
    int i = blockIdx.x * 256 + threadIdx.x;
    if (i < nE) atomicAdd(&g_cnt[rows[i]], 1);
}

__global__ void __launch_bounds__(SCAN_B) scan1_kernel() {
    __shared__ int s[SCAN_B];
    int t = threadIdx.x;
    int i = blockIdx.x * SCAN_B + t;
    int v = (i < NNODES) ? g_cnt[i] : 0;
    s[t] = v;
    __syncthreads();
#pragma unroll
    for (int off = 1; off < SCAN_B; off <<= 1) {
        int u = (t >= off) ? s[t - off] : 0;
        __syncthreads();
        s[t] += u;
        __syncthreads();
    }
    if (i < NNODES) g_off[i] = s[t] - v;          // exclusive
    if (t == SCAN_B - 1) g_bsum[blockIdx.x] = s[t];
}

__global__ void __launch_bounds__(128) scan2_kernel() {
    __shared__ int s[128];
    int t = threadIdx.x;
    int v = (t < NBLK) ? g_bsum[t] : 0;
    s[t] = v;
    __syncthreads();
#pragma unroll
    for (int off = 1; off < 128; off <<= 1) {
        int u = (t >= off) ? s[t - off] : 0;
        __syncthreads();
        s[t] += u;
        __syncthreads();
    }
    g_bsumx[t] = s[t] - v;                        // exclusive
}

__global__ void __launch_bounds__(256) scan3_kernel() {
    int i = blockIdx.x * 256 + threadIdx.x;
    if (i < NNODES) g_off[i] += g_bsumx[i >> 10];
}

__global__ void __launch_bounds__(256) scatter_kernel(
    const int* __restrict__ rows, const int* __restrict__ cols,
    const float* __restrict__ vals, int nE) {
    int i = blockIdx.x * 256 + threadIdx.x;
    if (i < nE) {
        int r = rows[i];
        int p = atomicAdd(&g_off[r], 1);
        g_srow[p] = r;
        g_scol[p] = cols[i];
        g_sval[p] = vals[i];
    }
}

// ---------------------------------------------------------------------------
// SpMM over row-sorted edges:  Y[r,:] += scale * val * X[c,:]
// One warp per 32 consecutive edges; same-row runs accumulate in registers,
// REDs only fire at row boundaries (~2-3 per warp-chunk instead of 32).
// ---------------------------------------------------------------------------
__global__ void __launch_bounds__(256) spmm_sorted_kernel(
    const float4* __restrict__ X,
    float4*       __restrict__ Y,
    float scale, int nE)
{
    __shared__ int   s_r[256];
    __shared__ int   s_c[256];
    __shared__ float s_v[256];

    int base = blockIdx.x * 256;
    int tid  = threadIdx.x;
    int rem  = nE - base;
    if (rem > 256) rem = 256;
    if (tid < rem) {
        s_r[tid] = g_srow[base + tid];
        s_c[tid] = g_scol[base + tid];
        s_v[tid] = g_sval[base + tid] * scale;
    }
    __syncthreads();

    int lane = tid & 31;
    int warp = tid >> 5;
    int e0   = warp * 32;
    int cnt  = rem - e0;
    if (cnt > 32) cnt = 32;
    if (cnt <= 0) return;

    float4 acc = make_float4(0.f, 0.f, 0.f, 0.f);
    int cur = s_r[e0];

    for (int j = 0; j < cnt; ++j) {
        int e = e0 + j;
        int r = s_r[e];
        if (r != cur) {
            float4* dst = &Y[cur * 32 + lane];
            asm volatile("red.global.add.v4.f32 [%0], {%1,%2,%3,%4};"
                         :: "l"(dst), "f"(acc.x), "f"(acc.y),
                            "f"(acc.z), "f"(acc.w) : "memory");
            acc = make_float4(0.f, 0.f, 0.f, 0.f);
            cur = r;
        }
        float v = s_v[e];
        int   c = s_c[e];
        float4 xv = __ldg(&X[c * 32 + lane]);
        acc.x = fmaf(xv.x, v, acc.x);
        acc.y = fmaf(xv.y, v, acc.y);
        acc.z = fmaf(xv.z, v, acc.z);
        acc.w = fmaf(xv.w, v, acc.w);
    }
    float4* dst = &Y[cur * 32 + lane];
    asm volatile("red.global.add.v4.f32 [%0], {%1,%2,%3,%4};"
                 :: "l"(dst), "f"(acc.x), "f"(acc.y),
                    "f"(acc.z), "f"(acc.w) : "memory");
}

// ---------------------------------------------------------------------------
// tf32 tensor-core GEMM (unchanged from R15):
//   out[n][o] = b[o] + sum_{k'} A[n][k'] * Wt2[k'][o],  A=[x|T1|T2|T3]
// ---------------------------------------------------------------------------
#define SA 36
#define SW 136

__global__ void __launch_bounds__(256, 2) gemm_kernel(
    const float* __restrict__ A0,
    const float* __restrict__ bias,
    float* __restrict__ out, int nNodes)
{
    __shared__ float sA[128 * SA];
    __shared__ float sW[32  * SW];

    const uint32_t* sAu = (const uint32_t*)sA;
    const uint32_t* sWu = (const uint32_t*)sW;

    int tid  = threadIdx.x;
    int lane = tid & 31;
    int warp = tid >> 5;
    int wm   = warp >> 1;
    int wn   = warp & 1;
    int m0   = blockIdx.x * 128;

    int g  = lane >> 2;
    int tg = lane & 3;

    float acc[2][8][4];
#pragma unroll
    for (int mt = 0; mt < 2; ++mt)
#pragma unroll
        for (int nt = 0; nt < 8; ++nt)
#pragma unroll
            for (int r = 0; r < 4; ++r) acc[mt][nt][r] = 0.f;

    const float* Abufs[4] = { A0, g_T1, g_T2, g_T3 };

#pragma unroll 1
    for (int ord = 0; ord < 4; ++ord) {
        const float4* Ab = (const float4*)Abufs[ord];
#pragma unroll 1
        for (int cc = 0; cc < 4; ++cc) {
            int kc = cc * 32;
            int kb = ord * 128 + kc;
            __syncthreads();
#pragma unroll
            for (int t = 0; t < 4; ++t) {
                int i   = tid + t * 256;
                int row = i >> 3;
                int fq  = i & 7;
                int gr  = m0 + row;
                if (gr >= nNodes) gr = nNodes - 1;
                float4 v = __ldg(&Ab[gr * 32 + (kc >> 2) + fq]);
                float* d = &sA[row * SA + fq * 4];
                d[0] = to_tf32(v.x); d[1] = to_tf32(v.y);
                d[2] = to_tf32(v.z); d[3] = to_tf32(v.w);
            }
            {
                const float4* src = (const float4*)g_Wt;
#pragma unroll
                for (int t = 0; t < 4; ++t) {
                    int i  = tid + t * 256;
                    int k  = i >> 5;
                    int o4 = i & 31;
                    float4 v = src[(kb + k) * 32 + o4];
                    *(float4*)&sW[k * SW + o4 * 4] = v;
                }
            }
            __syncthreads();

#pragma unroll
            for (int ks = 0; ks < 4; ++ks) {
                int k0 = ks * 8;
                uint32_t a[2][4];
#pragma unroll
                for (int mt = 0; mt < 2; ++mt) {
                    int r = wm * 32 + mt * 16 + g;
                    a[mt][0] = sAu[ r      * SA + k0 + tg    ];
                    a[mt][1] = sAu[(r + 8) * SA + k0 + tg    ];
                    a[mt][2] = sAu[ r      * SA + k0 + tg + 4];
                    a[mt][3] = sAu[(r + 8) * SA + k0 + tg + 4];
                }
#pragma unroll
                for (int nt = 0; nt < 8; ++nt) {
                    int col = wn * 64 + nt * 8 + g;
                    uint32_t b0 = sWu[(k0 + tg    ) * SW + col];
                    uint32_t b1 = sWu[(k0 + tg + 4) * SW + col];
#pragma unroll
                    for (int mt = 0; mt < 2; ++mt) {
                        asm volatile(
                            "mma.sync.aligned.m16n8k8.row.col.f32.tf32.tf32.f32 "
                            "{%0,%1,%2,%3}, {%4,%5,%6,%7}, {%8,%9}, {%0,%1,%2,%3};"
                            : "+f"(acc[mt][nt][0]), "+f"(acc[mt][nt][1]),
                              "+f"(acc[mt][nt][2]), "+f"(acc[mt][nt][3])
                            : "r"(a[mt][0]), "r"(a[mt][1]),
                              "r"(a[mt][2]), "r"(a[mt][3]),
                              "r"(b0), "r"(b1));
                    }
                }
            }
        }
    }

#pragma unroll
    for (int nt = 0; nt < 8; ++nt) {
        int col = wn * 64 + nt * 8 + tg * 2;
        float b0 = __ldg(&bias[col]);
        float b1 = __ldg(&bias[col + 1]);
#pragma unroll
        for (int mt = 0; mt < 2; ++mt) {
            int row = m0 + wm * 32 + mt * 16 + g;
            if (row < nNodes) {
                float2 v0 = make_float2(acc[mt][nt][0] + b0, acc[mt][nt][1] + b1);
                *(float2*)&out[row * 128 + col] = v0;
            }
            if (row + 8 < nNodes) {
                float2 v1 = make_float2(acc[mt][nt][2] + b0, acc[mt][nt][3] + b1);
                *(float2*)&out[(row + 8) * 128 + col] = v1;
            }
        }
    }
}

// ---------------------------------------------------------------------------
// Launch. Inputs (metadata order): x, lap_rows, lap_cols, lap_vals, W, b, k
// ---------------------------------------------------------------------------
extern "C" void kernel_launch(void* const* d_in, const int* in_sizes, int n_in,
                              void* d_out, int out_size) {
    const float* x    = (const float*)d_in[0];
    const int*   rows = (const int*)  d_in[1];
    const int*   cols = (const int*)  d_in[2];
    const float* vals = (const float*)d_in[3];
    const float* W    = (const float*)d_in[4];
    const float* b    = (const float*)d_in[5];
    float* out = (float*)d_out;

    int nNodes = in_sizes[0] / FDIM;     // 100000
    int E      = in_sizes[1];            // 3,200,000
    int n4     = nNodes * (FDIM / 4);

    float *T1, *T2, *T3;
    cudaGetSymbolAddress((void**)&T1, g_T1);
    cudaGetSymbolAddress((void**)&T2, g_T2);
    cudaGetSymbolAddress((void**)&T3, g_T3);

    int nb4 = (n4 + 255) / 256;
    int eb  = (E + 255) / 256;
    int nbn = (NNODES + 255) / 256;

    // T1 = 0, T2 = -x, cnt = 0 ; Wt = permuted tf32 W^T
    init_kernel<<<nb4, 256>>>((const float4*)x, n4);
    wt_kernel<<<256, 256>>>(W);

    // Counting sort of edges by row
    hist_kernel<<<eb, 256>>>(rows, E);
    scan1_kernel<<<NBLK, SCAN_B>>>();
    scan2_kernel<<<1, 128>>>();
    scan3_kernel<<<nbn, 256>>>();
    scatter_kernel<<<eb, 256>>>(rows, cols, vals, E);

    // T1 = L x
    spmm_sorted_kernel<<<eb, 256>>>((const float4*)x, (float4*)T1, 1.0f, E);
    // T3 = -T1
    neg_kernel<<<nb4, 256>>>(n4);
    // T2 = 2 L T1 - x   (T2 was -x)
    spmm_sorted_kernel<<<eb, 256>>>((const float4*)T1, (float4*)T2, 2.0f, E);
    // T3 = 2 L T2 - T1  (T3 was -T1)
    spmm_sorted_kernel<<<eb, 256>>>((const float4*)T2, (float4*)T3, 2.0f, E);

    // out = [x|T1|T2|T3] @ Wt2 + b   (tf32 tensor cores)
    gemm_kernel<<<(nNodes + 127) / 128, 256>>>(x, b, out, nNodes);
}